// round 17
// baseline (speedup 1.0000x reference)
#include <cuda_runtime.h>
#include <cuda_bf16.h>
#include <math.h>

// Problem constants: N=32768, M=8192, D=384, K=9
#define NN 32768
#define MM 8192
#define DD 384
#define KK 9

#define BM 64                  // embedding rows per CTA
#define BN 128                 // bank cols per tile
#define NKC 6                  // 64-wide k chunks
#define NMIT (MM / BN)         // 64
#define AKB (DD / 16)          // 24 A k-blocks
#define BKB (DD / 32)          // 12 B k-blocks
#define CAND_STRIDE 145        // 16 lists * 9 + 1

// Fragment-packed operands in global memory:
// g_Ap[rowBlk(16 rows)][kBlk(16)][lane 32][4 u32]  -> one LDG.128 = a0..a3
// g_Bp[colBlk(8 cols)][kBlk(32)][lane 32][4 u32]   -> one LDG.128 = b0,b1 for 2 k-steps
__device__ __align__(16) unsigned g_Ap[(size_t)(NN / 16) * AKB * 128];
__device__ __align__(16) unsigned g_Bp[(size_t)(MM / 8) * BKB * 128];
__device__ __align__(16) float g_xnorm[NN];
__device__ __align__(16) float g_ynorm[MM];

#define MMA4(d, av, b0, b1) \
    asm volatile("mma.sync.aligned.m16n8k16.row.col.f32.bf16.bf16.f32 " \
        "{%0,%1,%2,%3}, {%4,%5,%6,%7}, {%8,%9}, {%0,%1,%2,%3};" \
        : "+f"((d)[0]), "+f"((d)[1]), "+f"((d)[2]), "+f"((d)[3]) \
        : "r"((av).x), "r"((av).y), "r"((av).z), "r"((av).w), "r"(b0), "r"(b1))

// ---------------- convert + norm + fragment-pack pre-pass ----------------
// warp per row. Each thread handles 6 even-k pairs (k = 2*(lane + 32j)).
__global__ void conv_all(const float* __restrict__ x, const float* __restrict__ y) {
    const int bid = blockIdx.x;
    const int t = threadIdx.x;
    const bool isA = bid < NN / 8;
    const float* src;
    int row;
    if (isA) { row = bid * 8 + threadIdx.y; src = x; }
    else     { row = (bid - NN / 8) * 8 + threadIdx.y; src = y; }

    const float2* s2 = (const float2*)(src + (size_t)row * DD);
    float s = 0.f;
#pragma unroll
    for (int j = 0; j < 6; ++j) {
        int kp = t + 32 * j;
        int k = kp * 2;
        float2 v = s2[kp];
        s += v.x * v.x + v.y * v.y;
        __nv_bfloat162 bv = __floats2bfloat162_rn(v.x, v.y);
        unsigned val = *(unsigned*)&bv;
        if (isA) {
            // m16n8k16 A fragment: lane = (row%8)*4 + (k%8)/2,
            // slot = a0..a3 selected by (k/8, row/8)
            int blk  = (row >> 4) * AKB + (k >> 4);
            int lane = ((row & 7) << 2) | ((k & 7) >> 1);
            int slot = (((k >> 3) & 1) << 1) | ((row >> 3) & 1);
            g_Ap[(size_t)blk * 128 + lane * 4 + slot] = val;
        } else {
            // B fragment: lane = col*4 + (k%8)/2, slot = (k/8)%4
            int blk  = (row >> 3) * BKB + (k >> 5);
            int lane = ((row & 7) << 2) | ((k & 7) >> 1);
            int slot = (k >> 3) & 3;
            g_Bp[(size_t)blk * 128 + lane * 4 + slot] = val;
        }
    }
#pragma unroll
    for (int o = 16; o > 0; o >>= 1) s += __shfl_xor_sync(0xFFFFFFFFu, s, o);
    if (t == 0) (isA ? g_xnorm : g_ynorm)[row] = s;
}

// Rare path: branchless sorted shift, executed only when v < t[KK-1].
__device__ __forceinline__ void top9_shift(float* t, float v) {
#pragma unroll
    for (int p = KK - 1; p > 0; --p)
        t[p] = (v < t[p - 1]) ? t[p - 1] : fminf(v, t[p]);
    t[0] = fminf(t[0], v);
}

// ---------------- main fused kernel ----------------
// 256 threads = 8 warps = 2 (M) x 4 (N), warp tile 32x32, 2 CTAs/SM.
// All operands arrive via coalesced LDG.128 from fragment-packed global
// (L1/L2-resident). NO smem staging, NO barriers in the main loop.
__global__ void __launch_bounds__(256, 2) fapm_mma(float* __restrict__ out) {
    __shared__ float cand[BM * CAND_STRIDE];

    const int tid = threadIdx.x;
    const int l = tid & 31;
    const int w = tid >> 5;
    const int wm = w >> 2;     // 0..1 : M position (32 rows each)
    const int wn = w & 3;      // 0..3 : N position (32 cols each)
    const int row0 = blockIdx.x * BM;

    // xn for this thread's 4 rows: row0 + wm*32 + b*16 + h*8 + (l>>2)
    float xn[4];
#pragma unroll
    for (int b = 0; b < 2; ++b)
#pragma unroll
        for (int h = 0; h < 2; ++h)
            xn[b * 2 + h] = g_xnorm[row0 + wm * 32 + b * 16 + h * 8 + (l >> 2)];

    // fragment base pointers (uint4 granularity: blk*32 + lane)
    const uint4* Ap = ((const uint4*)g_Ap) + (size_t)(((row0 >> 4) + wm * 2) * AKB) * 32 + l;
    const uint4* Bp = ((const uint4*)g_Bp) + (size_t)(wn * 4 * BKB) * 32 + l;

    float tk[4][KK];
    float thr[4];
#pragma unroll
    for (int g = 0; g < 4; ++g) {
        thr[g] = 3.4e38f;
#pragma unroll
        for (int j = 0; j < KK; ++j) tk[g][j] = 3.4e38f;
    }

    float acc[2][4][4];
#pragma unroll
    for (int b = 0; b < 2; ++b)
#pragma unroll
        for (int i = 0; i < 4; ++i)
#pragma unroll
            for (int q = 0; q < 4; ++q) acc[b][i][q] = 0.f;

#pragma unroll 1
    for (int mi = 0; mi < NMIT; ++mi) {
#pragma unroll
        for (int c = 0; c < NKC; ++c) {
#pragma unroll
            for (int p = 0; p < 2; ++p) {
                // B fragments for 4 n-groups, k-steps 2p and 2p+1
                uint4 B0 = __ldg(Bp + (size_t)(0 * BKB + c * 2 + p) * 32);
                uint4 B1 = __ldg(Bp + (size_t)(1 * BKB + c * 2 + p) * 32);
                uint4 B2 = __ldg(Bp + (size_t)(2 * BKB + c * 2 + p) * 32);
                uint4 B3 = __ldg(Bp + (size_t)(3 * BKB + c * 2 + p) * 32);
#pragma unroll
                for (int q = 0; q < 2; ++q) {   // k-step within pair
                    int kb = c * 4 + p * 2 + q;
                    uint4 Aa = __ldg(Ap + (size_t)kb * 32);
                    uint4 Ab = __ldg(Ap + (size_t)(AKB + kb) * 32);
                    unsigned b00 = q ? B0.z : B0.x, b01 = q ? B0.w : B0.y;
                    unsigned b10 = q ? B1.z : B1.x, b11 = q ? B1.w : B1.y;
                    unsigned b20 = q ? B2.z : B2.x, b21 = q ? B2.w : B2.y;
                    unsigned b30 = q ? B3.z : B3.x, b31 = q ? B3.w : B3.y;
                    MMA4(acc[0][0], Aa, b00, b01);
                    MMA4(acc[0][1], Aa, b10, b11);
                    MMA4(acc[0][2], Aa, b20, b21);
                    MMA4(acc[0][3], Aa, b30, b31);
                    MMA4(acc[1][0], Ab, b00, b01);
                    MMA4(acc[1][1], Ab, b10, b11);
                    MMA4(acc[1][2], Ab, b20, b21);
                    MMA4(acc[1][3], Ab, b30, b31);
                }
            }
        }

        // ---- epilogue: fold tile into per-thread top-9 ----
        {
            const float2* ynp = (const float2*)(g_ynorm + mi * BN + wn * 32);
#pragma unroll
            for (int i = 0; i < 4; ++i) {
                float2 yn = __ldg(&ynp[i * 4 + (l & 3)]);
#pragma unroll
                for (int b = 0; b < 2; ++b) {
                    float* ac = acc[b][i];
                    float v;
                    v = fmaf(-2.f, ac[0], xn[b * 2 + 0] + yn.x);
                    if (v < thr[b * 2 + 0]) { top9_shift(tk[b * 2 + 0], v); thr[b * 2 + 0] = tk[b * 2 + 0][KK - 1]; }
                    v = fmaf(-2.f, ac[1], xn[b * 2 + 0] + yn.y);
                    if (v < thr[b * 2 + 0]) { top9_shift(tk[b * 2 + 0], v); thr[b * 2 + 0] = tk[b * 2 + 0][KK - 1]; }
                    v = fmaf(-2.f, ac[2], xn[b * 2 + 1] + yn.x);
                    if (v < thr[b * 2 + 1]) { top9_shift(tk[b * 2 + 1], v); thr[b * 2 + 1] = tk[b * 2 + 1][KK - 1]; }
                    v = fmaf(-2.f, ac[3], xn[b * 2 + 1] + yn.y);
                    if (v < thr[b * 2 + 1]) { top9_shift(tk[b * 2 + 1], v); thr[b * 2 + 1] = tk[b * 2 + 1][KK - 1]; }
                    ac[0] = 0.f; ac[1] = 0.f; ac[2] = 0.f; ac[3] = 0.f;
                }
            }
        }
        Bp += (size_t)16 * BKB * 32;   // next 128-col tile
    }

    // ---- merge 16 per-thread lists per row ----
    const int lst = wn * 4 + (l & 3);   // 0..15
#pragma unroll
    for (int b = 0; b < 2; ++b)
#pragma unroll
        for (int h = 0; h < 2; ++h) {
            int r = wm * 32 + b * 16 + h * 8 + (l >> 2);
#pragma unroll
            for (int j = 0; j < KK; ++j)
                cand[r * CAND_STRIDE + lst * KK + j] = tk[b * 2 + h][j];
        }
    __syncthreads();

    if (tid < BM) {
        float* c = &cand[tid * CAND_STRIDE];
        float* o = out + (size_t)(row0 + tid) * KK;
        const int NC = 16 * KK;   // 144
#pragma unroll 1
        for (int k = 0; k < KK; ++k) {
            float mv = c[k];
            int mi2 = k;
            for (int j = k + 1; j < NC; ++j) {
                float v = c[j];
                if (v < mv) { mv = v; mi2 = j; }
            }
            c[mi2] = c[k];
            c[k] = mv;
            o[k] = sqrtf(fmaxf(mv, 0.f));
        }
    }
}

extern "C" void kernel_launch(void* const* d_in, const int* in_sizes, int n_in,
                              void* d_out, int out_size) {
    const float* emb = (const float*)d_in[0];   // [N, D] fp32
    const float* mem = (const float*)d_in[1];   // [M, D] fp32
    float* out = (float*)d_out;                 // [N, K] fp32

    dim3 cb(32, 8);
    conv_all<<<NN / 8 + MM / 8, cb>>>(emb, mem);

    fapm_mma<<<NN / BM, 256>>>(out);
}